// round 15
// baseline (speedup 1.0000x reference)
#include <cuda_runtime.h>
#include <cuda_fp16.h>
#include <cstdint>

#define FDIM 128
#define MAXN 50176   // 50000 rounded up to 128-row tiles
#define PAD  136     // smem row pitch in halves (LDSM conflict-free)
#define CAP  80      // bucket slots per source node (Poisson(32): P(>80) ~ 1e-11)
#define SPILLCAP 8192

// Scratch (allocation-free rule: __device__ globals)
__device__ __half g_Wsh[FDIM * FDIM];          // Ws = W + W^T, fp16
__device__ __half g_Gh[(size_t)MAXN * FDIM];   // G = X@Ws, fp16
__device__ __half g_Xh[(size_t)MAXN * FDIM];   // X copy, fp16
__device__ int    g_idx64;                     // 1 if indices are int64
__device__ int    g_cnt[MAXN];                 // edges per source node
__device__ uint2  g_bucket[(size_t)MAXN * CAP]; // (j, mol) per slot  (~32MB)
__device__ int    g_spillcnt;
__device__ uint4  g_spill[SPILLCAP];           // (i, j, mol, -) overflow edges

// ---------------------------------------------------------------------------
// Kernel 0: detect index dtype (validated in R6: data is int32).
// ---------------------------------------------------------------------------
__global__ void detect_kernel(const void* __restrict__ mol, long long E) {
    const int* p = (const int*)mol;
    __shared__ int nonzero;
    if (threadIdx.x == 0) nonzero = 0;
    __syncthreads();
    long long half = E / 2;
    for (int s = threadIdx.x; s < 1024; s += blockDim.x) {
        long long e = (half * s) / 1024;
        if (p[2 * e + 1] != 0) atomicExch(&nonzero, 1);
    }
    __syncthreads();
    if (threadIdx.x == 0) g_idx64 = (nonzero == 0) ? 1 : 0;
}

// ---------------------------------------------------------------------------
// Kernel 1: Wsh = fp16(W + W^T)
// ---------------------------------------------------------------------------
__global__ void ws_kernel(const float* __restrict__ W) {
    int i = blockIdx.x;
    int j = threadIdx.x;
    g_Wsh[i * FDIM + j] = __float2half_rn(W[i * FDIM + j] + W[j * FDIM + i]);
}

// ---------------------------------------------------------------------------
// Kernel 1b: X -> fp16 copy
// ---------------------------------------------------------------------------
__global__ void x2h_kernel(const float* __restrict__ X, long long nvec4) {
    long long t = (long long)blockIdx.x * blockDim.x + threadIdx.x;
    if (t < nvec4) {
        float4 v = ((const float4*)X)[t];
        __half2 h0 = __floats2half2_rn(v.x, v.y);
        __half2 h1 = __floats2half2_rn(v.z, v.w);
        uint2 o;
        o.x = *(unsigned*)&h0;
        o.y = *(unsigned*)&h1;
        ((uint2*)g_Xh)[t] = o;
    }
}

// ---------------------------------------------------------------------------
// Kernel 1c: zero bucket counters + spill counter
// ---------------------------------------------------------------------------
__global__ void zero_kernel(int n) {
    int t = blockIdx.x * blockDim.x + threadIdx.x;
    if (t < n) g_cnt[t] = 0;
    if (t == 0) g_spillcnt = 0;
}

// ---------------------------------------------------------------------------
// Kernel 2: G = Xh @ Wsh via HMMA mma.sync.m16n8k16 (fp16 in, fp32 accum).
// ---------------------------------------------------------------------------
__device__ __forceinline__ void ldsm_x4(uint32_t addr, unsigned& r0, unsigned& r1,
                                        unsigned& r2, unsigned& r3) {
    asm volatile("ldmatrix.sync.aligned.m8n8.x4.shared.b16 {%0,%1,%2,%3}, [%4];"
                 : "=r"(r0), "=r"(r1), "=r"(r2), "=r"(r3) : "r"(addr));
}

__device__ __forceinline__ void ldsm_x4_t(uint32_t addr, unsigned& r0, unsigned& r1,
                                          unsigned& r2, unsigned& r3) {
    asm volatile("ldmatrix.sync.aligned.m8n8.x4.trans.shared.b16 {%0,%1,%2,%3}, [%4];"
                 : "=r"(r0), "=r"(r1), "=r"(r2), "=r"(r3) : "r"(addr));
}

__device__ __forceinline__ void mma16816(float* c, unsigned a0, unsigned a1,
                                         unsigned a2, unsigned a3,
                                         unsigned b0, unsigned b1) {
    asm volatile(
        "mma.sync.aligned.m16n8k16.row.col.f32.f16.f16.f32 "
        "{%0,%1,%2,%3}, {%4,%5,%6,%7}, {%8,%9}, {%0,%1,%2,%3};"
        : "+f"(c[0]), "+f"(c[1]), "+f"(c[2]), "+f"(c[3])
        : "r"(a0), "r"(a1), "r"(a2), "r"(a3), "r"(b0), "r"(b1));
}

__global__ __launch_bounds__(256) void gemm_kernel(int N) {
    extern __shared__ __align__(16) __half smem[];
    __half* Xs  = smem;                 // 128 x PAD
    __half* Wss = smem + 128 * PAD;     // 128 x PAD

    const int tid  = threadIdx.x;
    const int row0 = blockIdx.x * 128;

    for (int t = tid; t < 128 * 16; t += 256) {
        int r = t >> 4, c = t & 15;
        *(uint4*)&Wss[r * PAD + c * 8] = ((const uint4*)g_Wsh)[r * 16 + c];
    }
    for (int t = tid; t < 128 * 16; t += 256) {
        int r = t >> 4, c = t & 15;
        int gr = row0 + r;
        uint4 v = (gr < N) ? ((const uint4*)g_Xh)[(size_t)gr * 16 + c]
                           : make_uint4(0u, 0u, 0u, 0u);
        *(uint4*)&Xs[r * PAD + c * 8] = v;
    }
    __syncthreads();

    const int warp = tid >> 5;
    const int lane = tid & 31;
    const int wrow = warp * 16;
    const int g    = lane >> 3;

    const int aRow  = wrow + (lane & 7) + ((g & 1) ? 8 : 0);
    const int aKoff = (g >= 2) ? 8 : 0;
    const int bK    = (lane & 7) + ((g & 1) ? 8 : 0);
    const int bNoff = (g >= 2) ? 8 : 0;

    const uint32_t xsBase = (uint32_t)__cvta_generic_to_shared(Xs);
    const uint32_t wsBase = (uint32_t)__cvta_generic_to_shared(Wss);

    float c[16][4];
#pragma unroll
    for (int n = 0; n < 16; n++)
#pragma unroll
        for (int q = 0; q < 4; q++) c[n][q] = 0.f;

#pragma unroll
    for (int k0 = 0; k0 < 128; k0 += 16) {
        unsigned a0, a1, a2, a3;
        ldsm_x4(xsBase + (uint32_t)(aRow * PAD + k0 + aKoff) * 2, a0, a1, a2, a3);
#pragma unroll
        for (int nt = 0; nt < 16; nt += 2) {
            unsigned b0, b1, b2, b3;
            ldsm_x4_t(wsBase + (uint32_t)((bK + k0) * PAD + nt * 8 + bNoff) * 2,
                      b0, b1, b2, b3);
            mma16816(c[nt],     a0, a1, a2, a3, b0, b1);
            mma16816(c[nt + 1], a0, a1, a2, a3, b2, b3);
        }
    }

    const int erow = wrow + (lane >> 2);
    const int ecol4 = lane & 3;
#pragma unroll
    for (int nt = 0; nt < 16; nt++) {
        int colh = nt * 4 + ecol4;
        int gr0 = row0 + erow;
        int gr1 = gr0 + 8;
        if (gr0 < N) {
            __half2 h = __floats2half2_rn(c[nt][0], c[nt][1]);
            ((unsigned*)g_Gh)[(size_t)gr0 * 64 + colh] = *(unsigned*)&h;
        }
        if (gr1 < N) {
            __half2 h = __floats2half2_rn(c[nt][2], c[nt][3]);
            ((unsigned*)g_Gh)[(size_t)gr1 * 64 + colh] = *(unsigned*)&h;
        }
    }
}

// ---------------------------------------------------------------------------
// Kernel 3: scatter edges into per-source-node buckets (canonical int32).
// ---------------------------------------------------------------------------
__global__ void scatter_kernel(const void* __restrict__ nbr,
                               const void* __restrict__ mol, long long E) {
    long long e = (long long)blockIdx.x * blockDim.x + threadIdx.x;
    if (e >= E) return;
    int i, j, m;
    if (g_idx64 == 0) {
        const int* src = (const int*)nbr;
        i = src[e];
        j = src[E + e];
        m = ((const int*)mol)[e];
    } else {
        const long long* src = (const long long*)nbr;
        i = (int)src[e];
        j = (int)src[E + e];
        m = (int)((const long long*)mol)[e];
    }
    int pos = atomicAdd(&g_cnt[i], 1);
    if (pos < CAP) {
        g_bucket[(size_t)i * CAP + pos] = make_uint2((unsigned)j, (unsigned)m);
    } else {
        int sp = atomicAdd(&g_spillcnt, 1);
        if (sp < SPILLCAP)
            g_spill[sp] = make_uint4((unsigned)i, (unsigned)j, (unsigned)m, 0u);
    }
}

// ---------------------------------------------------------------------------
// Kernel 4: process — half-warp per source row. G[i] loaded ONCE into
// registers, reused across all ~32 partners. Inner loop unrolled x4:
// 4 LDG.128 of X[j] in flight per half-warp. Partial-mask butterfly
// reduce, per-edge smem atomic, block flush to out.
// ---------------------------------------------------------------------------
__device__ __forceinline__ float hdot8(uint4 ua, uint4 ub) {
    float2 a0 = __half22float2(*(const __half2*)&ua.x);
    float2 a1 = __half22float2(*(const __half2*)&ua.y);
    float2 a2 = __half22float2(*(const __half2*)&ua.z);
    float2 a3 = __half22float2(*(const __half2*)&ua.w);
    float2 b0 = __half22float2(*(const __half2*)&ub.x);
    float2 b1 = __half22float2(*(const __half2*)&ub.y);
    float2 b2 = __half22float2(*(const __half2*)&ub.z);
    float2 b3 = __half22float2(*(const __half2*)&ub.w);
    float s = a0.x * b0.x;
    s = fmaf(a0.y, b0.y, s);
    s = fmaf(a1.x, b1.x, s);
    s = fmaf(a1.y, b1.y, s);
    s = fmaf(a2.x, b2.x, s);
    s = fmaf(a2.y, b2.y, s);
    s = fmaf(a3.x, b3.x, s);
    s = fmaf(a3.y, b3.y, s);
    return s;
}

__global__ __launch_bounds__(256)
void process_kernel(int N, float* __restrict__ out, int M) {
    extern __shared__ float acc[];
    for (int t = threadIdx.x; t < M; t += blockDim.x) acc[t] = 0.f;
    __syncthreads();

    const int lane = threadIdx.x & 31;
    const int half = lane >> 4;
    const int hl   = lane & 15;
    const unsigned hm = 0xFFFFu << (half * 16);
    const uint4* __restrict__ A = (const uint4*)g_Gh;
    const uint4* __restrict__ B = (const uint4*)g_Xh;

    long long hw  = ((long long)blockIdx.x * blockDim.x + threadIdx.x) >> 4;
    long long nhw = ((long long)gridDim.x * blockDim.x) >> 4;

    for (long long r = hw; r < N; r += nhw) {
        int cnt = g_cnt[r];
        if (cnt > CAP) cnt = CAP;
        if (cnt == 0) continue;

        uint4 gi = A[(size_t)r * 16 + hl];            // G row resident in regs
        const uint2* __restrict__ bk = g_bucket + (size_t)r * CAP;

        for (int base = 0; base < cnt; base += 16) {
            int nb = cnt - base;
            if (nb > 16) nb = 16;
            uint2 jm = (hl < nb) ? bk[base + hl] : make_uint2(0u, 0u);
            int myj = (int)jm.x;
            int mym = (int)jm.y;

            int p = 0;
            for (; p + 4 <= nb; p += 4) {
                int j0 = __shfl_sync(hm, myj, p,     16);
                int j1 = __shfl_sync(hm, myj, p + 1, 16);
                int j2 = __shfl_sync(hm, myj, p + 2, 16);
                int j3 = __shfl_sync(hm, myj, p + 3, 16);
                uint4 x0 = B[(size_t)j0 * 16 + hl];
                uint4 x1 = B[(size_t)j1 * 16 + hl];
                uint4 x2 = B[(size_t)j2 * 16 + hl];
                uint4 x3 = B[(size_t)j3 * 16 + hl];
                float s0 = hdot8(gi, x0);
                float s1 = hdot8(gi, x1);
                float s2 = hdot8(gi, x2);
                float s3 = hdot8(gi, x3);
#pragma unroll
                for (int o = 8; o; o >>= 1) {
                    s0 += __shfl_xor_sync(hm, s0, o);
                    s1 += __shfl_xor_sync(hm, s1, o);
                    s2 += __shfl_xor_sync(hm, s2, o);
                    s3 += __shfl_xor_sync(hm, s3, o);
                }
                int m0 = __shfl_sync(hm, mym, p,     16);
                int m1 = __shfl_sync(hm, mym, p + 1, 16);
                int m2 = __shfl_sync(hm, mym, p + 2, 16);
                int m3 = __shfl_sync(hm, mym, p + 3, 16);
                if (hl == 0) {
                    atomicAdd(&acc[m0], s0);
                    atomicAdd(&acc[m1], s1);
                    atomicAdd(&acc[m2], s2);
                    atomicAdd(&acc[m3], s3);
                }
            }
            for (; p < nb; p++) {
                int j0 = __shfl_sync(hm, myj, p, 16);
                uint4 x0 = B[(size_t)j0 * 16 + hl];
                float s0 = hdot8(gi, x0);
#pragma unroll
                for (int o = 8; o; o >>= 1) s0 += __shfl_xor_sync(hm, s0, o);
                int m0 = __shfl_sync(hm, mym, p, 16);
                if (hl == 0) atomicAdd(&acc[m0], s0);
            }
        }
    }

    __syncthreads();
    for (int t = threadIdx.x; t < M; t += blockDim.x)
        atomicAdd(&out[t], acc[t]);
}

// ---------------------------------------------------------------------------
// Kernel 5: spill edges (bucket overflow) — almost always zero entries.
// ---------------------------------------------------------------------------
__global__ void spill_kernel(float* __restrict__ out) {
    const int lane = threadIdx.x & 31;
    const int half = lane >> 4;
    const int hl   = lane & 15;
    const unsigned hm = 0xFFFFu << (half * 16);
    const uint4* __restrict__ A = (const uint4*)g_Gh;
    const uint4* __restrict__ B = (const uint4*)g_Xh;

    int n = g_spillcnt;
    if (n > SPILLCAP) n = SPILLCAP;
    long long hw  = ((long long)blockIdx.x * blockDim.x + threadIdx.x) >> 4;
    long long nhw = ((long long)gridDim.x * blockDim.x) >> 4;

    for (long long e = hw; e < n; e += nhw) {
        uint4 ent = g_spill[e];
        uint4 a = A[(size_t)ent.x * 16 + hl];
        uint4 b = B[(size_t)ent.y * 16 + hl];
        float s = hdot8(a, b);
#pragma unroll
        for (int o = 8; o; o >>= 1) s += __shfl_xor_sync(hm, s, o);
        if (hl == 0) atomicAdd(&out[ent.z], s);
    }
}

// ---------------------------------------------------------------------------
// Launch
// ---------------------------------------------------------------------------
extern "C" void kernel_launch(void* const* d_in, const int* in_sizes, int n_in,
                              void* d_out, int out_size) {
    const float* X  = (const float*)d_in[0];   // [N, 128] fp32
    const float* W  = (const float*)d_in[1];   // [128, 128] fp32
    const void*  nbr = d_in[2];                // [2, E] int32 (detected) or int64
    const void*  mol = d_in[3];                // [E]
    float* out = (float*)d_out;                // [M] fp32

    const long long E = (long long)in_sizes[3];
    const int N = in_sizes[0] / FDIM;

    cudaMemsetAsync(d_out, 0, (size_t)out_size * sizeof(float), 0);

    detect_kernel<<<1, 256>>>(mol, E);
    ws_kernel<<<FDIM, FDIM>>>(W);

    long long nvec4 = (long long)N * FDIM / 4;
    x2h_kernel<<<(int)((nvec4 + 255) / 256), 256>>>(X, nvec4);

    zero_kernel<<<(N + 255) / 256, 256>>>(N);

    size_t gemm_smem = (size_t)2 * 128 * PAD * sizeof(__half);
    cudaFuncSetAttribute(gemm_kernel, cudaFuncAttributeMaxDynamicSharedMemorySize,
                         (int)gemm_smem);
    int gemm_blocks = (N + 127) / 128;
    gemm_kernel<<<gemm_blocks, 256, gemm_smem>>>(N);

    scatter_kernel<<<(int)((E + 255) / 256), 256>>>(nbr, mol, E);

    size_t smem = (size_t)out_size * sizeof(float);
    int pblocks = (int)(((long long)N * 16 + 255) / 256);   // half-warp per row
    process_kernel<<<pblocks, 256, smem>>>(N, out, out_size);

    spill_kernel<<<16, 256>>>(out);
}

// round 16
// speedup vs baseline: 1.0104x; 1.0104x over previous
#include <cuda_runtime.h>
#include <cuda_fp16.h>
#include <cstdint>

#define FDIM 128
#define MAXN 50176   // 50000 rounded up to 128-row tiles
#define PAD  136     // smem row pitch in halves (LDSM conflict-free)
#define CAP  80      // bucket slots per source node (Poisson(32): P(>80) ~ 1e-11)
#define SPILLCAP 8192

// Scratch (allocation-free rule: __device__ globals)
__device__ __half g_Wsh[FDIM * FDIM];          // Ws = W + W^T, fp16
__device__ __half g_Gh[(size_t)MAXN * FDIM];   // G = X@Ws, fp16
__device__ __half g_Xh[(size_t)MAXN * FDIM];   // X copy, fp16
__device__ int    g_idx64;                     // 1 if indices are int64
__device__ int    g_cnt[MAXN];                 // edges per source node
__device__ uint2  g_bucket[(size_t)MAXN * CAP]; // (j, mol) per slot  (~32MB)
__device__ int    g_spillcnt;
__device__ uint4  g_spill[SPILLCAP];           // (i, j, mol, -) overflow edges

// ---------------------------------------------------------------------------
// Kernel 0: detect index dtype (validated in R6: data is int32).
// ---------------------------------------------------------------------------
__global__ void detect_kernel(const void* __restrict__ mol, long long E) {
    const int* p = (const int*)mol;
    __shared__ int nonzero;
    if (threadIdx.x == 0) nonzero = 0;
    __syncthreads();
    long long half = E / 2;
    for (int s = threadIdx.x; s < 1024; s += blockDim.x) {
        long long e = (half * s) / 1024;
        if (p[2 * e + 1] != 0) atomicExch(&nonzero, 1);
    }
    __syncthreads();
    if (threadIdx.x == 0) g_idx64 = (nonzero == 0) ? 1 : 0;
}

// ---------------------------------------------------------------------------
// Kernel 1: Wsh = fp16(W + W^T)
// ---------------------------------------------------------------------------
__global__ void ws_kernel(const float* __restrict__ W) {
    int i = blockIdx.x;
    int j = threadIdx.x;
    g_Wsh[i * FDIM + j] = __float2half_rn(W[i * FDIM + j] + W[j * FDIM + i]);
}

// ---------------------------------------------------------------------------
// Kernel 1b: X -> fp16 copy, plus bucket-counter zeroing (folded, free)
// ---------------------------------------------------------------------------
__global__ void x2h_kernel(const float* __restrict__ X, long long nvec4, int N) {
    long long t = (long long)blockIdx.x * blockDim.x + threadIdx.x;
    if (t < nvec4) {
        float4 v = ((const float4*)X)[t];
        __half2 h0 = __floats2half2_rn(v.x, v.y);
        __half2 h1 = __floats2half2_rn(v.z, v.w);
        uint2 o;
        o.x = *(unsigned*)&h0;
        o.y = *(unsigned*)&h1;
        ((uint2*)g_Xh)[t] = o;
    }
    if (t < N) g_cnt[t] = 0;
    if (t == 0) g_spillcnt = 0;
}

// ---------------------------------------------------------------------------
// Kernel 2: G = Xh @ Wsh via HMMA mma.sync.m16n8k16 (fp16 in, fp32 accum).
// ---------------------------------------------------------------------------
__device__ __forceinline__ void ldsm_x4(uint32_t addr, unsigned& r0, unsigned& r1,
                                        unsigned& r2, unsigned& r3) {
    asm volatile("ldmatrix.sync.aligned.m8n8.x4.shared.b16 {%0,%1,%2,%3}, [%4];"
                 : "=r"(r0), "=r"(r1), "=r"(r2), "=r"(r3) : "r"(addr));
}

__device__ __forceinline__ void ldsm_x4_t(uint32_t addr, unsigned& r0, unsigned& r1,
                                          unsigned& r2, unsigned& r3) {
    asm volatile("ldmatrix.sync.aligned.m8n8.x4.trans.shared.b16 {%0,%1,%2,%3}, [%4];"
                 : "=r"(r0), "=r"(r1), "=r"(r2), "=r"(r3) : "r"(addr));
}

__device__ __forceinline__ void mma16816(float* c, unsigned a0, unsigned a1,
                                         unsigned a2, unsigned a3,
                                         unsigned b0, unsigned b1) {
    asm volatile(
        "mma.sync.aligned.m16n8k16.row.col.f32.f16.f16.f32 "
        "{%0,%1,%2,%3}, {%4,%5,%6,%7}, {%8,%9}, {%0,%1,%2,%3};"
        : "+f"(c[0]), "+f"(c[1]), "+f"(c[2]), "+f"(c[3])
        : "r"(a0), "r"(a1), "r"(a2), "r"(a3), "r"(b0), "r"(b1));
}

__global__ __launch_bounds__(256) void gemm_kernel(int N) {
    extern __shared__ __align__(16) __half smem[];
    __half* Xs  = smem;                 // 128 x PAD
    __half* Wss = smem + 128 * PAD;     // 128 x PAD

    const int tid  = threadIdx.x;
    const int row0 = blockIdx.x * 128;

    for (int t = tid; t < 128 * 16; t += 256) {
        int r = t >> 4, c = t & 15;
        *(uint4*)&Wss[r * PAD + c * 8] = ((const uint4*)g_Wsh)[r * 16 + c];
    }
    for (int t = tid; t < 128 * 16; t += 256) {
        int r = t >> 4, c = t & 15;
        int gr = row0 + r;
        uint4 v = (gr < N) ? ((const uint4*)g_Xh)[(size_t)gr * 16 + c]
                           : make_uint4(0u, 0u, 0u, 0u);
        *(uint4*)&Xs[r * PAD + c * 8] = v;
    }
    __syncthreads();

    const int warp = tid >> 5;
    const int lane = tid & 31;
    const int wrow = warp * 16;
    const int g    = lane >> 3;

    const int aRow  = wrow + (lane & 7) + ((g & 1) ? 8 : 0);
    const int aKoff = (g >= 2) ? 8 : 0;
    const int bK    = (lane & 7) + ((g & 1) ? 8 : 0);
    const int bNoff = (g >= 2) ? 8 : 0;

    const uint32_t xsBase = (uint32_t)__cvta_generic_to_shared(Xs);
    const uint32_t wsBase = (uint32_t)__cvta_generic_to_shared(Wss);

    float c[16][4];
#pragma unroll
    for (int n = 0; n < 16; n++)
#pragma unroll
        for (int q = 0; q < 4; q++) c[n][q] = 0.f;

#pragma unroll
    for (int k0 = 0; k0 < 128; k0 += 16) {
        unsigned a0, a1, a2, a3;
        ldsm_x4(xsBase + (uint32_t)(aRow * PAD + k0 + aKoff) * 2, a0, a1, a2, a3);
#pragma unroll
        for (int nt = 0; nt < 16; nt += 2) {
            unsigned b0, b1, b2, b3;
            ldsm_x4_t(wsBase + (uint32_t)((bK + k0) * PAD + nt * 8 + bNoff) * 2,
                      b0, b1, b2, b3);
            mma16816(c[nt],     a0, a1, a2, a3, b0, b1);
            mma16816(c[nt + 1], a0, a1, a2, a3, b2, b3);
        }
    }

    const int erow = wrow + (lane >> 2);
    const int ecol4 = lane & 3;
#pragma unroll
    for (int nt = 0; nt < 16; nt++) {
        int colh = nt * 4 + ecol4;
        int gr0 = row0 + erow;
        int gr1 = gr0 + 8;
        if (gr0 < N) {
            __half2 h = __floats2half2_rn(c[nt][0], c[nt][1]);
            ((unsigned*)g_Gh)[(size_t)gr0 * 64 + colh] = *(unsigned*)&h;
        }
        if (gr1 < N) {
            __half2 h = __floats2half2_rn(c[nt][2], c[nt][3]);
            ((unsigned*)g_Gh)[(size_t)gr1 * 64 + colh] = *(unsigned*)&h;
        }
    }
}

// ---------------------------------------------------------------------------
// Kernel 3: scatter edges into per-source-node buckets (canonical int32).
// ---------------------------------------------------------------------------
__global__ void scatter_kernel(const void* __restrict__ nbr,
                               const void* __restrict__ mol, long long E) {
    long long e = (long long)blockIdx.x * blockDim.x + threadIdx.x;
    if (e >= E) return;
    int i, j, m;
    if (g_idx64 == 0) {
        const int* src = (const int*)nbr;
        i = src[e];
        j = src[E + e];
        m = ((const int*)mol)[e];
    } else {
        const long long* src = (const long long*)nbr;
        i = (int)src[e];
        j = (int)src[E + e];
        m = (int)((const long long*)mol)[e];
    }
    int pos = atomicAdd(&g_cnt[i], 1);
    if (pos < CAP) {
        g_bucket[(size_t)i * CAP + pos] = make_uint2((unsigned)j, (unsigned)m);
    } else {
        int sp = atomicAdd(&g_spillcnt, 1);
        if (sp < SPILLCAP)
            g_spill[sp] = make_uint4((unsigned)i, (unsigned)j, (unsigned)m, 0u);
    }
}

// ---------------------------------------------------------------------------
// Kernel 4: process — half-warp per source row, grid-stride. G[i] loaded
// ONCE into registers, reused across all ~32 partners. Unroll x4 keeps
// 4 LDG.128 of X[j] in flight per half-warp. Owning-lane atomic commit
// (no m shuffles). 592 blocks only -> final flush is 0.6M atomics.
// ---------------------------------------------------------------------------
__device__ __forceinline__ float hdot8(uint4 ua, uint4 ub) {
    float2 a0 = __half22float2(*(const __half2*)&ua.x);
    float2 a1 = __half22float2(*(const __half2*)&ua.y);
    float2 a2 = __half22float2(*(const __half2*)&ua.z);
    float2 a3 = __half22float2(*(const __half2*)&ua.w);
    float2 b0 = __half22float2(*(const __half2*)&ub.x);
    float2 b1 = __half22float2(*(const __half2*)&ub.y);
    float2 b2 = __half22float2(*(const __half2*)&ub.z);
    float2 b3 = __half22float2(*(const __half2*)&ub.w);
    float s = a0.x * b0.x;
    s = fmaf(a0.y, b0.y, s);
    s = fmaf(a1.x, b1.x, s);
    s = fmaf(a1.y, b1.y, s);
    s = fmaf(a2.x, b2.x, s);
    s = fmaf(a2.y, b2.y, s);
    s = fmaf(a3.x, b3.x, s);
    s = fmaf(a3.y, b3.y, s);
    return s;
}

__global__ __launch_bounds__(256)
void process_kernel(int N, float* __restrict__ out, int M) {
    extern __shared__ float acc[];
    for (int t = threadIdx.x; t < M; t += blockDim.x) acc[t] = 0.f;
    __syncthreads();

    const int lane = threadIdx.x & 31;
    const int half = lane >> 4;
    const int hl   = lane & 15;
    const unsigned hm = 0xFFFFu << (half * 16);
    const uint4* __restrict__ A = (const uint4*)g_Gh;
    const uint4* __restrict__ B = (const uint4*)g_Xh;

    long long hw  = ((long long)blockIdx.x * blockDim.x + threadIdx.x) >> 4;
    long long nhw = ((long long)gridDim.x * blockDim.x) >> 4;

    for (long long r = hw; r < N; r += nhw) {
        int cnt = g_cnt[r];
        if (cnt > CAP) cnt = CAP;
        if (cnt == 0) continue;

        uint4 gi = A[(size_t)r * 16 + hl];            // G row resident in regs
        const uint2* __restrict__ bk = g_bucket + (size_t)r * CAP;

        for (int base = 0; base < cnt; base += 16) {
            int nb = cnt - base;
            if (nb > 16) nb = 16;
            uint2 jm = (hl < nb) ? bk[base + hl] : make_uint2(0u, 0u);
            int myj = (int)jm.x;
            int mym = (int)jm.y;

            int p = 0;
            for (; p + 4 <= nb; p += 4) {
                int j0 = __shfl_sync(hm, myj, p,     16);
                int j1 = __shfl_sync(hm, myj, p + 1, 16);
                int j2 = __shfl_sync(hm, myj, p + 2, 16);
                int j3 = __shfl_sync(hm, myj, p + 3, 16);
                uint4 x0 = B[(size_t)j0 * 16 + hl];
                uint4 x1 = B[(size_t)j1 * 16 + hl];
                uint4 x2 = B[(size_t)j2 * 16 + hl];
                uint4 x3 = B[(size_t)j3 * 16 + hl];
                float s0 = hdot8(gi, x0);
                float s1 = hdot8(gi, x1);
                float s2 = hdot8(gi, x2);
                float s3 = hdot8(gi, x3);
#pragma unroll
                for (int o = 8; o; o >>= 1) {
                    s0 += __shfl_xor_sync(hm, s0, o);
                    s1 += __shfl_xor_sync(hm, s1, o);
                    s2 += __shfl_xor_sync(hm, s2, o);
                    s3 += __shfl_xor_sync(hm, s3, o);
                }
                // Owning lane commits its edge (reduced value is in all lanes)
                if (hl >= p && hl < p + 4) {
                    float sv = (hl == p)     ? s0
                             : (hl == p + 1) ? s1
                             : (hl == p + 2) ? s2 : s3;
                    atomicAdd(&acc[mym], sv);
                }
            }
            for (; p < nb; p++) {
                int j0 = __shfl_sync(hm, myj, p, 16);
                uint4 x0 = B[(size_t)j0 * 16 + hl];
                float s0 = hdot8(gi, x0);
#pragma unroll
                for (int o = 8; o; o >>= 1) s0 += __shfl_xor_sync(hm, s0, o);
                if (hl == p) atomicAdd(&acc[mym], s0);
            }
        }
    }

    __syncthreads();
    for (int t = threadIdx.x; t < M; t += blockDim.x)
        atomicAdd(&out[t], acc[t]);
}

// ---------------------------------------------------------------------------
// Kernel 5: spill edges (bucket overflow) — almost always zero entries.
// ---------------------------------------------------------------------------
__global__ void spill_kernel(float* __restrict__ out) {
    const int lane = threadIdx.x & 31;
    const int half = lane >> 4;
    const int hl   = lane & 15;
    const unsigned hm = 0xFFFFu << (half * 16);
    const uint4* __restrict__ A = (const uint4*)g_Gh;
    const uint4* __restrict__ B = (const uint4*)g_Xh;

    int n = g_spillcnt;
    if (n > SPILLCAP) n = SPILLCAP;
    long long hw  = ((long long)blockIdx.x * blockDim.x + threadIdx.x) >> 4;
    long long nhw = ((long long)gridDim.x * blockDim.x) >> 4;

    for (long long e = hw; e < n; e += nhw) {
        uint4 ent = g_spill[e];
        uint4 a = A[(size_t)ent.x * 16 + hl];
        uint4 b = B[(size_t)ent.y * 16 + hl];
        float s = hdot8(a, b);
#pragma unroll
        for (int o = 8; o; o >>= 1) s += __shfl_xor_sync(hm, s, o);
        if (hl == 0) atomicAdd(&out[ent.z], s);
    }
}

// ---------------------------------------------------------------------------
// Launch
// ---------------------------------------------------------------------------
extern "C" void kernel_launch(void* const* d_in, const int* in_sizes, int n_in,
                              void* d_out, int out_size) {
    const float* X  = (const float*)d_in[0];   // [N, 128] fp32
    const float* W  = (const float*)d_in[1];   // [128, 128] fp32
    const void*  nbr = d_in[2];                // [2, E] int32 (detected) or int64
    const void*  mol = d_in[3];                // [E]
    float* out = (float*)d_out;                // [M] fp32

    const long long E = (long long)in_sizes[3];
    const int N = in_sizes[0] / FDIM;

    cudaMemsetAsync(d_out, 0, (size_t)out_size * sizeof(float), 0);

    detect_kernel<<<1, 256>>>(mol, E);
    ws_kernel<<<FDIM, FDIM>>>(W);

    long long nvec4 = (long long)N * FDIM / 4;
    x2h_kernel<<<(int)((nvec4 + 255) / 256), 256>>>(X, nvec4, N);

    size_t gemm_smem = (size_t)2 * 128 * PAD * sizeof(__half);
    cudaFuncSetAttribute(gemm_kernel, cudaFuncAttributeMaxDynamicSharedMemorySize,
                         (int)gemm_smem);
    int gemm_blocks = (N + 127) / 128;
    gemm_kernel<<<gemm_blocks, 256, gemm_smem>>>(N);

    scatter_kernel<<<(int)((E + 255) / 256), 256>>>(nbr, mol, E);

    // 592 blocks grid-striding over rows: flush = 0.6M global atomics (not 3.2M)
    size_t smem = (size_t)out_size * sizeof(float);
    process_kernel<<<592, 256, smem>>>(N, out, out_size);

    spill_kernel<<<16, 256>>>(out);
}